// round 6
// baseline (speedup 1.0000x reference)
#include <cuda_runtime.h>
#include <cstdint>

// Problem constants
#define B_ROWS    1024
#define IN_FEAT   76800
#define IN_G      19200     // IN_FEAT/4 (float4 / int8x4 groups)
#define OUT_FEAT  10
#define W_ELEMS   (OUT_FEAT * IN_FEAT)   // 768000
#define W_G       (OUT_FEAT * IN_G)      // 192000 packed groups

// rowmax kernel
#define QT        768
#define QK        25                     // 25*768 = 19200

// gemv kernel: 8 slices x 37 rowblocks = 296 CTAs = 2/SM (round-4 proven shape)
#define NSLICE    8
#define SLICE_G   (IN_G / NSLICE)        // 2400 groups
#define GT        480
#define GPT       (SLICE_G / GT)         // 5 k-steps/thread
#define ROWBLK    37
// smem: weight quads [10][GT] uint4 (k=0..3) + singles [10][GT] u32 (k=4) = 96000B
#define SWQ_WORDS (OUT_FEAT * GT * 4)
#define GEMV_SMEM ((SWQ_WORDS + OUT_FEAT * GT) * 4)

// wsum reduction
#define WSUM_BLOCKS 125
#define WSUM_THREADS 256

// ---------------- device scratch (static, allocation-free) ----------------
__device__ float    g_wpart[WSUM_BLOCKS];
__device__ float    g_wscale;               // 1/clip(mean|W|,eps)
__device__ float    g_winv;                 // clip(mean|W|,eps)
__device__ float    g_rowscale[B_ROWS];     // 127/clip(rowmax,eps)
__device__ unsigned g_tw[W_G];              // ternary weights, packed int8x4, [o][g]
__device__ int      g_dot[B_ROWS * OUT_FEAT];

// ---------------- kernel 1: sum |W| ----------------
__global__ void k_wsum(const float4* __restrict__ w4) {
    float s = 0.f;
    int idx = blockIdx.x * WSUM_THREADS + threadIdx.x;
    #pragma unroll
    for (int k = 0; k < 6; k++) {   // 125*256*6 = 192000 exactly
        float4 v = w4[idx + k * WSUM_BLOCKS * WSUM_THREADS];
        s += fabsf(v.x) + fabsf(v.y) + fabsf(v.z) + fabsf(v.w);
    }
    #pragma unroll
    for (int d = 16; d; d >>= 1) s += __shfl_down_sync(0xffffffffu, s, d);
    __shared__ float red[8];
    int warp = threadIdx.x >> 5, lane = threadIdx.x & 31;
    if (lane == 0) red[warp] = s;
    __syncthreads();
    if (threadIdx.x < 8) {
        float v = red[threadIdx.x];
        #pragma unroll
        for (int d = 4; d; d >>= 1) v += __shfl_down_sync(0xffu, v, d);
        if (threadIdx.x == 0) g_wpart[blockIdx.x] = v;
    }
}

// ---------------- kernel 2: finalize wscale ----------------
__global__ void k_wscale(void) {
    float s = (threadIdx.x < WSUM_BLOCKS) ? g_wpart[threadIdx.x] : 0.f;
    #pragma unroll
    for (int d = 16; d; d >>= 1) s += __shfl_down_sync(0xffffffffu, s, d);
    __shared__ float red[4];
    int warp = threadIdx.x >> 5, lane = threadIdx.x & 31;
    if (lane == 0) red[warp] = s;
    __syncthreads();
    if (threadIdx.x == 0) {
        float total = red[0] + red[1] + red[2] + red[3];
        float mean = fmaxf(total / (float)W_ELEMS, 1e-5f);
        g_winv = mean;
        g_wscale = 1.f / mean;
    }
}

// ---------------- kernel 3: ternarize W into packed int8x4 ----------------
__global__ void k_ternary(const float4* __restrict__ w4) {
    int i = blockIdx.x * 256 + threadIdx.x;   // grid 750*256 = 192000
    float ws = g_wscale;
    float4 v = w4[i];
    int t0 = (int)fminf(1.f, fmaxf(-1.f, rintf(v.x * ws)));
    int t1 = (int)fminf(1.f, fmaxf(-1.f, rintf(v.y * ws)));
    int t2 = (int)fminf(1.f, fmaxf(-1.f, rintf(v.z * ws)));
    int t3 = (int)fminf(1.f, fmaxf(-1.f, rintf(v.w * ws)));
    g_tw[i] = (unsigned)((t0 & 0xFF) | ((t1 & 0xFF) << 8) | ((t2 & 0xFF) << 16) | (t3 << 24));
}

// ---------------- kernel 4: per-row absmax (measured at DRAM roofline) ----------------
// Also zeroes g_dot for this row.
__global__ void __launch_bounds__(QT) k_rowmax(const float4* __restrict__ x4) {
    const int row = blockIdx.x;
    const int tid = threadIdx.x;
    if (tid < OUT_FEAT) g_dot[row * OUT_FEAT + tid] = 0;

    const float4* xr = x4 + (size_t)row * IN_G;
    float m = 0.f;
    #pragma unroll 5
    for (int k = 0; k < QK; k++) {
        float4 v = xr[tid + k * QT];
        m = fmaxf(m, fmaxf(fmaxf(fabsf(v.x), fabsf(v.y)),
                           fmaxf(fabsf(v.z), fabsf(v.w))));
    }
    #pragma unroll
    for (int d = 16; d; d >>= 1) m = fmaxf(m, __shfl_down_sync(0xffffffffu, m, d));
    __shared__ float red[QT / 32];
    int warp = tid >> 5, lane = tid & 31;
    if (lane == 0) red[warp] = m;
    __syncthreads();
    if (tid < 32) {
        float v = (tid < QT / 32) ? red[tid] : 0.f;
        #pragma unroll
        for (int d = 16; d; d >>= 1) v = fmaxf(v, __shfl_down_sync(0xffffffffu, v, d));
        if (tid == 0) g_rowscale[row] = 127.f / fmaxf(v, 1e-5f);
    }
}

// magic-number quantize: FMUL+FADD(1.5*2^23) == round-half-even of fl(x*s)
// for |x*s|<=127 (validated rel_err 5.9e-7).
__device__ __forceinline__ unsigned quant_pack(float4 v, float as) {
    float f0 = __fadd_rn(__fmul_rn(v.x, as), 12582912.f);
    float f1 = __fadd_rn(__fmul_rn(v.y, as), 12582912.f);
    float f2 = __fadd_rn(__fmul_rn(v.z, as), 12582912.f);
    float f3 = __fadd_rn(__fmul_rn(v.w, as), 12582912.f);
    unsigned p01 = __byte_perm(__float_as_uint(f0), __float_as_uint(f1), 0x0040);
    unsigned p23 = __byte_perm(__float_as_uint(f2), __float_as_uint(f3), 0x0040);
    return __byte_perm(p01, p23, 0x5410);
}

// ---------------- kernel 5: fused quantize + ternary GEMV, 2-row pipeline ----------------
// 296 CTAs (2/SM, 30 warps/SM). Two NAMED register buffers (A/B) with only
// compile-time indexing -> no local memory. Next row's LDGs are issued before
// the current row's compute, so every warp keeps 2.5KB in flight during the
// quant/dp4a/reduce chain. No syncthreads in the loop.
__global__ void __launch_bounds__(GT, 2) k_gemv(const float4* __restrict__ x4) {
    extern __shared__ unsigned smem[];
    uint4*    swq = (uint4*)smem;                 // [10][GT] quads (k=0..3)
    unsigned* sws = smem + SWQ_WORDS;             // [10][GT] singles (k=4)

    const int s = blockIdx.x;
    const int rb = blockIdx.y;
    const int tid = threadIdx.x;
    const int lane = tid & 31;
    const int gbase = s * SLICE_G;

    // one-time weight staging
    #pragma unroll
    for (int o = 0; o < OUT_FEAT; o++) {
        uint4 w;
        w.x = g_tw[o * IN_G + gbase + 0 * GT + tid];
        w.y = g_tw[o * IN_G + gbase + 1 * GT + tid];
        w.z = g_tw[o * IN_G + gbase + 2 * GT + tid];
        w.w = g_tw[o * IN_G + gbase + 3 * GT + tid];
        swq[o * GT + tid] = w;
        sws[o * GT + tid] = g_tw[o * IN_G + gbase + 4 * GT + tid];
    }
    __syncthreads();

    const float4* xb = x4 + gbase + tid;   // thread-fixed base

    float4 A[GPT], Bb[GPT];
    float asA, asB;

    // compute-and-store for one ready buffer (compile-time buffer choice)
    #define GEMV_COMPUTE(BUF, AS, ROW)                                          \
    do {                                                                        \
        unsigned q[GPT];                                                        \
        _Pragma("unroll")                                                       \
        for (int k = 0; k < GPT; k++) q[k] = quant_pack(BUF[k], AS);            \
        int acc[OUT_FEAT];                                                      \
        _Pragma("unroll")                                                       \
        for (int o = 0; o < OUT_FEAT; o++) {                                    \
            uint4 w = swq[o * GT + tid];                                        \
            int a = __dp4a((int)q[0], (int)w.x, 0);                             \
            a = __dp4a((int)q[1], (int)w.y, a);                                 \
            a = __dp4a((int)q[2], (int)w.z, a);                                 \
            a = __dp4a((int)q[3], (int)w.w, a);                                 \
            acc[o] = __dp4a((int)q[4], (int)sws[o * GT + tid], a);              \
        }                                                                       \
        _Pragma("unroll")                                                       \
        for (int o = 0; o < OUT_FEAT; o++)                                      \
            acc[o] = __reduce_add_sync(0xffffffffu, acc[o]);                    \
        if (lane == 0) {                                                        \
            int* dst = g_dot + (ROW) * OUT_FEAT;                                \
            _Pragma("unroll")                                                   \
            for (int o = 0; o < OUT_FEAT; o++) atomicAdd(dst + o, acc[o]);      \
        }                                                                       \
    } while (0)

    #define GEMV_LOAD(BUF, AS, ROW)                                             \
    do {                                                                        \
        const float4* xr = xb + (size_t)(ROW) * IN_G;                           \
        _Pragma("unroll")                                                       \
        for (int k = 0; k < GPT; k++) BUF[k] = xr[k * GT];                      \
        AS = g_rowscale[ROW];                                                   \
    } while (0)

    // descending rows (harvest k_rowmax's L2 tail)
    int rowA = B_ROWS - 1 - rb;
    GEMV_LOAD(A, asA, rowA);

    for (;;) {
        int rowB = rowA - ROWBLK;
        if (rowB >= 0) GEMV_LOAD(Bb, asB, rowB);      // in flight during A's compute
        GEMV_COMPUTE(A, asA, rowA);
        if (rowB < 0) break;

        rowA = rowB - ROWBLK;
        if (rowA >= 0) GEMV_LOAD(A, asA, rowA);       // in flight during B's compute
        GEMV_COMPUTE(Bb, asB, rowB);
        if (rowA < 0) break;
    }
    #undef GEMV_COMPUTE
    #undef GEMV_LOAD
}

// ---------------- kernel 6: scale, bias, softmax ----------------
__global__ void k_finish(const float* __restrict__ bias, float* __restrict__ out) {
    int row = blockIdx.x * 128 + threadIdx.x;   // grid 8 x 128
    float inv_as = 1.f / g_rowscale[row];
    float coef = inv_as * g_winv;
    const int* dp = g_dot + row * OUT_FEAT;
    float logit[OUT_FEAT];
    float m = -3.4e38f;
    #pragma unroll
    for (int o = 0; o < OUT_FEAT; o++) {
        logit[o] = coef * (float)dp[o] + bias[o];
        m = fmaxf(m, logit[o]);
    }
    float ssum = 0.f;
    #pragma unroll
    for (int o = 0; o < OUT_FEAT; o++) { logit[o] = expf(logit[o] - m); ssum += logit[o]; }
    float inv_s = 1.f / ssum;
    #pragma unroll
    for (int o = 0; o < OUT_FEAT; o++) out[row * OUT_FEAT + o] = logit[o] * inv_s;
}

// ---------------- launch (fork/join: weight chain overlaps rowmax) ----------------
extern "C" void kernel_launch(void* const* d_in, const int* in_sizes, int n_in,
                              void* d_out, int out_size) {
    const float4* x4 = (const float4*)d_in[0];   // [1024,3,160,160] fp32
    const float4* w4 = (const float4*)d_in[1];   // [10,76800] fp32
    const float*  b  = (const float*)d_in[2];    // [10]
    float* out = (float*)d_out;

    static cudaStream_t s_side = nullptr;
    static cudaEvent_t ev_fork = nullptr, ev_join = nullptr;
    static int init_done = 0;
    if (!init_done) {
        cudaStreamCreateWithFlags(&s_side, cudaStreamNonBlocking);
        cudaEventCreateWithFlags(&ev_fork, cudaEventDisableTiming);
        cudaEventCreateWithFlags(&ev_join, cudaEventDisableTiming);
        cudaFuncSetAttribute(k_gemv, cudaFuncAttributeMaxDynamicSharedMemorySize, GEMV_SMEM);
        init_done = 1;
    }

    // fork: weight-prep chain on side stream, concurrent with k_rowmax
    cudaEventRecord(ev_fork, 0);
    cudaStreamWaitEvent(s_side, ev_fork, 0);
    k_wsum<<<WSUM_BLOCKS, WSUM_THREADS, 0, s_side>>>(w4);
    k_wscale<<<1, 128, 0, s_side>>>();
    k_ternary<<<W_G / 256, 256, 0, s_side>>>(w4);
    cudaEventRecord(ev_join, s_side);

    k_rowmax<<<B_ROWS, QT>>>(x4);                 // ~47us, hides the chain

    cudaStreamWaitEvent(0, ev_join, 0);
    dim3 ggrid(NSLICE, ROWBLK);
    k_gemv<<<ggrid, GT, GEMV_SMEM>>>(x4);
    k_finish<<<B_ROWS / 128, 128>>>(b, out);
}

// round 7
// speedup vs baseline: 1.6763x; 1.6763x over previous
#include <cuda_runtime.h>
#include <cstdint>

// Problem constants
#define B_ROWS    1024
#define IN_FEAT   76800
#define IN_G      19200     // IN_FEAT/4 (float4 / int8x4 groups)
#define OUT_FEAT  10
#define W_ELEMS   (OUT_FEAT * IN_FEAT)   // 768000
#define W_G       (OUT_FEAT * IN_G)      // 192000 packed groups

// rowmax kernel
#define QT        768
#define QK        25                     // 25*768 = 19200

// gemv kernel: 10 slices x 29 rowblocks = 290 CTAs (one wave at 2/SM), 384 thr
#define NSLICE    10
#define SLICE_G   (IN_G / NSLICE)        // 1920 groups
#define GT        384
#define GPT       (SLICE_G / GT)         // 5 k-steps/thread
#define ROWBLK    29
// smem: weight quads [10][GT] uint4 (k=0..3) + singles [10][GT] u32 (k=4)
#define SWQ_WORDS (OUT_FEAT * GT * 4)
#define GEMV_SMEM ((SWQ_WORDS + OUT_FEAT * GT) * 4)   // 76800 B

// wsum reduction
#define WSUM_BLOCKS 125
#define WSUM_THREADS 256

// ---------------- device scratch (static, allocation-free) ----------------
__device__ float    g_wpart[WSUM_BLOCKS];
__device__ float    g_wscale;               // 1/clip(mean|W|,eps)
__device__ float    g_winv;                 // clip(mean|W|,eps)
__device__ float    g_rowscale[B_ROWS];     // 127/clip(rowmax,eps)
__device__ unsigned g_tw[W_G];              // ternary weights, packed int8x4, [o][g]
__device__ int      g_dot[B_ROWS * OUT_FEAT];

// ---------------- kernel 1: sum |W| ----------------
__global__ void k_wsum(const float4* __restrict__ w4) {
    float s = 0.f;
    int idx = blockIdx.x * WSUM_THREADS + threadIdx.x;
    #pragma unroll
    for (int k = 0; k < 6; k++) {   // 125*256*6 = 192000 exactly
        float4 v = w4[idx + k * WSUM_BLOCKS * WSUM_THREADS];
        s += fabsf(v.x) + fabsf(v.y) + fabsf(v.z) + fabsf(v.w);
    }
    #pragma unroll
    for (int d = 16; d; d >>= 1) s += __shfl_down_sync(0xffffffffu, s, d);
    __shared__ float red[8];
    int warp = threadIdx.x >> 5, lane = threadIdx.x & 31;
    if (lane == 0) red[warp] = s;
    __syncthreads();
    if (threadIdx.x < 8) {
        float v = red[threadIdx.x];
        #pragma unroll
        for (int d = 4; d; d >>= 1) v += __shfl_down_sync(0xffu, v, d);
        if (threadIdx.x == 0) g_wpart[blockIdx.x] = v;
    }
}

// ---------------- kernel 2: finalize wscale ----------------
__global__ void k_wscale(void) {
    float s = (threadIdx.x < WSUM_BLOCKS) ? g_wpart[threadIdx.x] : 0.f;
    #pragma unroll
    for (int d = 16; d; d >>= 1) s += __shfl_down_sync(0xffffffffu, s, d);
    __shared__ float red[4];
    int warp = threadIdx.x >> 5, lane = threadIdx.x & 31;
    if (lane == 0) red[warp] = s;
    __syncthreads();
    if (threadIdx.x == 0) {
        float total = red[0] + red[1] + red[2] + red[3];
        float mean = fmaxf(total / (float)W_ELEMS, 1e-5f);
        g_winv = mean;
        g_wscale = 1.f / mean;
    }
}

// ---------------- kernel 3: ternarize W into packed int8x4 ----------------
__global__ void k_ternary(const float4* __restrict__ w4) {
    int i = blockIdx.x * 256 + threadIdx.x;   // grid 750*256 = 192000
    float ws = g_wscale;
    float4 v = w4[i];
    int t0 = (int)fminf(1.f, fmaxf(-1.f, rintf(v.x * ws)));
    int t1 = (int)fminf(1.f, fmaxf(-1.f, rintf(v.y * ws)));
    int t2 = (int)fminf(1.f, fmaxf(-1.f, rintf(v.z * ws)));
    int t3 = (int)fminf(1.f, fmaxf(-1.f, rintf(v.w * ws)));
    g_tw[i] = (unsigned)((t0 & 0xFF) | ((t1 & 0xFF) << 8) | ((t2 & 0xFF) << 16) | (t3 << 24));
}

// ---------------- kernel 4: per-row absmax (measured at DRAM roofline) ----------------
// Also zeroes g_dot for this row.
__global__ void __launch_bounds__(QT) k_rowmax(const float4* __restrict__ x4) {
    const int row = blockIdx.x;
    const int tid = threadIdx.x;
    if (tid < OUT_FEAT) g_dot[row * OUT_FEAT + tid] = 0;

    const float4* xr = x4 + (size_t)row * IN_G;
    float m = 0.f;
    #pragma unroll 5
    for (int k = 0; k < QK; k++) {
        float4 v = xr[tid + k * QT];
        m = fmaxf(m, fmaxf(fmaxf(fabsf(v.x), fabsf(v.y)),
                           fmaxf(fabsf(v.z), fabsf(v.w))));
    }
    #pragma unroll
    for (int d = 16; d; d >>= 1) m = fmaxf(m, __shfl_down_sync(0xffffffffu, m, d));
    __shared__ float red[QT / 32];
    int warp = tid >> 5, lane = tid & 31;
    if (lane == 0) red[warp] = m;
    __syncthreads();
    if (tid < 32) {
        float v = (tid < QT / 32) ? red[tid] : 0.f;
        #pragma unroll
        for (int d = 16; d; d >>= 1) v = fmaxf(v, __shfl_down_sync(0xffffffffu, v, d));
        if (tid == 0) g_rowscale[row] = 127.f / fmaxf(v, 1e-5f);
    }
}

// FMA magic-number quantize: round-to-nearest-even of x*as in one FFMA.
// (Single-rounded FMA vs ref's mul-then-round differs only within 2^-24 of tie
// boundaries — a handful of +/-1 LSB flips across 78M elements, invisible at 1e-3.)
__device__ __forceinline__ unsigned quant_pack(float4 v, float as) {
    float f0 = __fmaf_rn(v.x, as, 12582912.f);   // 1.5*2^23
    float f1 = __fmaf_rn(v.y, as, 12582912.f);
    float f2 = __fmaf_rn(v.z, as, 12582912.f);
    float f3 = __fmaf_rn(v.w, as, 12582912.f);
    unsigned p01 = __byte_perm(__float_as_uint(f0), __float_as_uint(f1), 0x0040);
    unsigned p23 = __byte_perm(__float_as_uint(f2), __float_as_uint(f3), 0x0040);
    return __byte_perm(p01, p23, 0x5410);
}

// ---------------- kernel 5: fused quantize + ternary GEMV, row-PAIR batched ----------------
// 290 CTAs (2/SM, 24 warps/SM, 85-reg cap -> no spills). Each iteration
// processes TWO rows: 10 LDG.128 issued up-front (5KB in flight/thread),
// each weight LDS serves both rows (smem traffic per row halved).
// Descending rows harvest k_rowmax's L2 tail. No syncthreads in the loop.
__global__ void __launch_bounds__(GT, 2) k_gemv(const float4* __restrict__ x4) {
    extern __shared__ unsigned smem[];
    uint4*    swq = (uint4*)smem;                 // [10][GT] quads (k=0..3)
    unsigned* sws = smem + SWQ_WORDS;             // [10][GT] singles (k=4)

    const int s = blockIdx.x;
    const int rb = blockIdx.y;
    const int tid = threadIdx.x;
    const int lane = tid & 31;
    const int gbase = s * SLICE_G;

    // one-time weight staging
    #pragma unroll
    for (int o = 0; o < OUT_FEAT; o++) {
        uint4 w;
        w.x = g_tw[o * IN_G + gbase + 0 * GT + tid];
        w.y = g_tw[o * IN_G + gbase + 1 * GT + tid];
        w.z = g_tw[o * IN_G + gbase + 2 * GT + tid];
        w.w = g_tw[o * IN_G + gbase + 3 * GT + tid];
        swq[o * GT + tid] = w;
        sws[o * GT + tid] = g_tw[o * IN_G + gbase + 4 * GT + tid];
    }
    __syncthreads();

    const float4* xb = x4 + gbase + tid;   // thread-fixed base

    int r0 = B_ROWS - 1 - rb;              // descending
    while (r0 >= 0) {
        const int r1 = r0 - ROWBLK;
        const int r1c = (r1 >= 0) ? r1 : r0;   // tail: duplicate row, skip 2nd atomic

        // issue all 10 LDGs up-front (5KB in flight per thread)
        float4 v0[GPT], v1[GPT];
        #pragma unroll
        for (int k = 0; k < GPT; k++) v0[k] = xb[(size_t)r0 * IN_G + k * GT];
        #pragma unroll
        for (int k = 0; k < GPT; k++) v1[k] = xb[(size_t)r1c * IN_G + k * GT];
        const float as0 = g_rowscale[r0];
        const float as1 = g_rowscale[r1c];

        unsigned q0[GPT], q1[GPT];
        #pragma unroll
        for (int k = 0; k < GPT; k++) { q0[k] = quant_pack(v0[k], as0);
                                        q1[k] = quant_pack(v1[k], as1); }

        // each weight load feeds BOTH rows
        int acc0[OUT_FEAT], acc1[OUT_FEAT];
        #pragma unroll
        for (int o = 0; o < OUT_FEAT; o++) {
            const uint4 w = swq[o * GT + tid];
            const int ws4 = (int)sws[o * GT + tid];
            int a0 = __dp4a((int)q0[0], (int)w.x, 0);
            int a1 = __dp4a((int)q1[0], (int)w.x, 0);
            a0 = __dp4a((int)q0[1], (int)w.y, a0);
            a1 = __dp4a((int)q1[1], (int)w.y, a1);
            a0 = __dp4a((int)q0[2], (int)w.z, a0);
            a1 = __dp4a((int)q1[2], (int)w.z, a1);
            a0 = __dp4a((int)q0[3], (int)w.w, a0);
            a1 = __dp4a((int)q1[3], (int)w.w, a1);
            acc0[o] = __dp4a((int)q0[4], ws4, a0);
            acc1[o] = __dp4a((int)q1[4], ws4, a1);
        }

        // warp reduce + exact integer atomics (order-independent)
        #pragma unroll
        for (int o = 0; o < OUT_FEAT; o++) {
            acc0[o] = __reduce_add_sync(0xffffffffu, acc0[o]);
            acc1[o] = __reduce_add_sync(0xffffffffu, acc1[o]);
        }
        if (lane == 0) {
            int* d0 = g_dot + r0 * OUT_FEAT;
            #pragma unroll
            for (int o = 0; o < OUT_FEAT; o++) atomicAdd(d0 + o, acc0[o]);
            if (r1 >= 0) {
                int* d1 = g_dot + r1 * OUT_FEAT;
                #pragma unroll
                for (int o = 0; o < OUT_FEAT; o++) atomicAdd(d1 + o, acc1[o]);
            }
        }
        r0 -= 2 * ROWBLK;
    }
}

// ---------------- kernel 6: scale, bias, softmax ----------------
__global__ void k_finish(const float* __restrict__ bias, float* __restrict__ out) {
    int row = blockIdx.x * 128 + threadIdx.x;   // grid 8 x 128
    float inv_as = 1.f / g_rowscale[row];
    float coef = inv_as * g_winv;
    const int* dp = g_dot + row * OUT_FEAT;
    float logit[OUT_FEAT];
    float m = -3.4e38f;
    #pragma unroll
    for (int o = 0; o < OUT_FEAT; o++) {
        logit[o] = coef * (float)dp[o] + bias[o];
        m = fmaxf(m, logit[o]);
    }
    float ssum = 0.f;
    #pragma unroll
    for (int o = 0; o < OUT_FEAT; o++) { logit[o] = expf(logit[o] - m); ssum += logit[o]; }
    float inv_s = 1.f / ssum;
    #pragma unroll
    for (int o = 0; o < OUT_FEAT; o++) out[row * OUT_FEAT + o] = logit[o] * inv_s;
}

// ---------------- launch (fork/join: weight chain overlaps rowmax) ----------------
extern "C" void kernel_launch(void* const* d_in, const int* in_sizes, int n_in,
                              void* d_out, int out_size) {
    const float4* x4 = (const float4*)d_in[0];   // [1024,3,160,160] fp32
    const float4* w4 = (const float4*)d_in[1];   // [10,76800] fp32
    const float*  b  = (const float*)d_in[2];    // [10]
    float* out = (float*)d_out;

    static cudaStream_t s_side = nullptr;
    static cudaEvent_t ev_fork = nullptr, ev_join = nullptr;
    static int init_done = 0;
    if (!init_done) {
        cudaStreamCreateWithFlags(&s_side, cudaStreamNonBlocking);
        cudaEventCreateWithFlags(&ev_fork, cudaEventDisableTiming);
        cudaEventCreateWithFlags(&ev_join, cudaEventDisableTiming);
        cudaFuncSetAttribute(k_gemv, cudaFuncAttributeMaxDynamicSharedMemorySize, GEMV_SMEM);
        init_done = 1;
    }

    // fork: weight-prep chain on side stream, concurrent with k_rowmax
    cudaEventRecord(ev_fork, 0);
    cudaStreamWaitEvent(s_side, ev_fork, 0);
    k_wsum<<<WSUM_BLOCKS, WSUM_THREADS, 0, s_side>>>(w4);
    k_wscale<<<1, 128, 0, s_side>>>();
    k_ternary<<<W_G / 256, 256, 0, s_side>>>(w4);
    cudaEventRecord(ev_join, s_side);

    k_rowmax<<<B_ROWS, QT>>>(x4);                 // ~47us, hides the chain

    cudaStreamWaitEvent(0, ev_join, 0);
    dim3 ggrid(NSLICE, ROWBLK);
    k_gemv<<<ggrid, GT, GEMV_SMEM>>>(x4);
    k_finish<<<B_ROWS / 128, 128>>>(b, out);
}